// round 12
// baseline (speedup 1.0000x reference)
#include <cuda_runtime.h>
#include <cuda_fp16.h>
#include <cstdint>
#include <cstddef>

#define CDIM 1024
#define HEADS 16
#define DHD 64
#define LSEQ 2048
#define BATCH 2
#define DFF 4096
#define NROWS (BATCH*LSEQ)   /* 4096 */

// ---------------- scratch (device globals: alloc-free) ----------------
__device__ float  g_ada[BATCH * 6 * CDIM];                  // [B,6,C]
__device__ float  g_bias3[3 * CDIM];                        // [q_bias, 0, v_bias]
__device__ float  g_x1[(size_t)NROWS * CDIM];               // residual stream f32
__device__ __half g_wh[12582912];                           // converted weights
__device__ __half g_abh[(size_t)LSEQ * LSEQ];               // attn_bias (half)
__device__ __half g_hh[(size_t)NROWS * CDIM];               // LN-mod out (half)
__device__ __half g_qkvh[(size_t)NROWS * 3 * CDIM];         // qkv (half)
__device__ __half g_attnh[(size_t)NROWS * CDIM];            // attn out (half)
__device__ __half g_ffh[(size_t)NROWS * DFF];               // fc1+gelu out (half)

#define WH_QKV  0
#define WH_PROJ 3145728
#define WH_FC1  4194304
#define WH_FC2  8388608

// ================= helpers =================
__device__ __forceinline__ uint32_t smem_u32(const void* p) {
    uint32_t a;
    asm("{ .reg .u64 t; cvta.to.shared.u64 t, %1; cvt.u32.u64 %0, t; }" : "=r"(a) : "l"(p));
    return a;
}
__device__ __forceinline__ void cpasync16(uint32_t dst, const void* src) {
    asm volatile("cp.async.cg.shared.global [%0], [%1], 16;" :: "r"(dst), "l"(src));
}
__device__ __forceinline__ void cp_commit() { asm volatile("cp.async.commit_group;" ::: "memory"); }
__device__ __forceinline__ void cp_wait2()  { asm volatile("cp.async.wait_group 2;" ::: "memory"); }
__device__ __forceinline__ void cp_wait1()  { asm volatile("cp.async.wait_group 1;" ::: "memory"); }

__device__ __forceinline__ uint32_t f2h2(float x, float y) {
    __half2 h = __floats2half2_rn(x, y);
    return *reinterpret_cast<uint32_t*>(&h);
}
__device__ __forceinline__ void mma_f16(float* c,
    uint32_t a0, uint32_t a1, uint32_t a2, uint32_t a3, uint32_t b0, uint32_t b1)
{
    asm volatile(
        "mma.sync.aligned.m16n8k16.row.col.f32.f16.f16.f32 "
        "{%0,%1,%2,%3},{%4,%5,%6,%7},{%8,%9},{%0,%1,%2,%3};"
        : "+f"(c[0]), "+f"(c[1]), "+f"(c[2]), "+f"(c[3])
        : "r"(a0), "r"(a1), "r"(a2), "r"(a3), "r"(b0), "r"(b1));
}
__device__ __forceinline__ void ldsm_x4(uint32_t& r0, uint32_t& r1, uint32_t& r2, uint32_t& r3,
                                        uint32_t addr) {
    asm volatile("ldmatrix.sync.aligned.m8n8.x4.shared.b16 {%0,%1,%2,%3}, [%4];"
        : "=r"(r0), "=r"(r1), "=r"(r2), "=r"(r3) : "r"(addr));
}
__device__ __forceinline__ void ldsm_x4_t(uint32_t& r0, uint32_t& r1, uint32_t& r2, uint32_t& r3,
                                          uint32_t addr) {
    asm volatile("ldmatrix.sync.aligned.m8n8.x4.trans.shared.b16 {%0,%1,%2,%3}, [%4];"
        : "=r"(r0), "=r"(r1), "=r"(r2), "=r"(r3) : "r"(addr));
}

// FMA-pipe exp (no MUFU), clamped both sides
__device__ __forceinline__ float fexp(float x) {
    float t = fminf(fmaxf(x, -87.f), 87.f) * 1.4426950408889634f;
    float z = __fadd_rn(t, 12582912.0f);
    float n = __fsub_rn(z, 12582912.0f);
    int ni = (__float_as_int(z) & 0x7FFFFF) - 0x400000;
    float c = (t - n) * 0.6931471805599453f;
    float p = 8.3333333e-3f;
    p = fmaf(p, c, 4.1666667e-2f);
    p = fmaf(p, c, 0.16666667f);
    p = fmaf(p, c, 0.5f);
    p = fmaf(p, c, 1.0f);
    p = fmaf(p, c, 1.0f);
    return p * __int_as_float((ni + 127) << 23);
}

// ---------------- combined f32 -> f16 convert: 4 weights + attn_bias ----------------
__global__ __launch_bounds__(256) void f2h_multi(
    const float4* __restrict__ s0, const float4* __restrict__ s1,
    const float4* __restrict__ s2, const float4* __restrict__ s3,
    const float4* __restrict__ s4,
    uint2* __restrict__ d0, uint2* __restrict__ d1, uint2* __restrict__ d2,
    uint2* __restrict__ d3, uint2* __restrict__ d4,
    int n0, int n1, int n2, int n3, int n4)
{
    int i = blockIdx.x * 256 + threadIdx.x;
    const float4* s; uint2* d;
    if (i < n0) { s = s0; d = d0; }
    else if ((i -= n0) < n1) { s = s1; d = d1; }
    else if ((i -= n1) < n2) { s = s2; d = d2; }
    else if ((i -= n2) < n3) { s = s3; d = d3; }
    else if ((i -= n3) < n4) { s = s4; d = d4; }
    else return;
    float4 v = s[i];
    d[i] = make_uint2(f2h2(v.x, v.y), f2h2(v.z, v.w));
}

// ---------------- bias3 = [q_bias, 0, v_bias] ----------------
__global__ __launch_bounds__(256) void bias3_kernel(
    const float* __restrict__ qb, const float* __restrict__ vb)
{
    int i = blockIdx.x * 256 + threadIdx.x;
    float v = 0.f;
    if (i < CDIM) v = qb[i];
    else if (i >= 2 * CDIM) v = vb[i - 2 * CDIM];
    g_bias3[i] = v;
}

// ---------------- ada = silu(cond) @ ada_w.T + ada_b ----------------
__global__ __launch_bounds__(128) void ada_kernel(
    const float* __restrict__ cond, const float* __restrict__ ada_w,
    const float* __restrict__ ada_b)
{
    const int warp = threadIdx.x >> 5;
    const int lane = threadIdx.x & 31;
    const int o = blockIdx.x * 4 + warp;
    const int b = blockIdx.y;
    const float* wr = ada_w + (size_t)o * CDIM;
    const float* cr = cond + b * CDIM;
    float s = 0.f;
    for (int k = lane; k < CDIM; k += 32) {
        float c = cr[k];
        float si = __fdividef(c, 1.f + fexp(-c));
        s += si * wr[k];
    }
    #pragma unroll
    for (int m = 16; m; m >>= 1) s += __shfl_xor_sync(0xffffffffu, s, m);
    if (lane == 0) g_ada[b * 6 * CDIM + o] = s + ada_b[o];
}

// ---------------- h = LN(x) * (scale+1) + shift  (half out) ----------------
__global__ __launch_bounds__(256) void ln_mod_kernel(
    const float* __restrict__ x, __half* __restrict__ h, int sc, int sh)
{
    __shared__ float red[2];
    const int row = blockIdx.x;
    const int b = row >> 11;
    const float* xr = x + (size_t)row * CDIM;
    float v[4];
    float s = 0.f, ss = 0.f;
    #pragma unroll
    for (int u = 0; u < 4; u++) {
        v[u] = xr[threadIdx.x + u * 256];
        s += v[u]; ss += v[u] * v[u];
    }
    #pragma unroll
    for (int m = 16; m; m >>= 1) {
        s  += __shfl_xor_sync(0xffffffffu, s, m);
        ss += __shfl_xor_sync(0xffffffffu, ss, m);
    }
    __shared__ float ws[16];
    int w = threadIdx.x >> 5, ln = threadIdx.x & 31;
    if (ln == 0) { ws[w] = s; ws[8 + w] = ss; }
    __syncthreads();
    if (threadIdx.x == 0) {
        float S = 0.f, SS = 0.f;
        #pragma unroll
        for (int i = 0; i < 8; i++) { S += ws[i]; SS += ws[8 + i]; }
        float m = S * (1.f / CDIM);
        float var = SS * (1.f / CDIM) - m * m;
        red[0] = m;
        red[1] = rsqrtf(var + 1e-6f);
    }
    __syncthreads();
    const float mean = red[0], rstd = red[1];
    const float* ap = g_ada + b * 6 * CDIM;
    #pragma unroll
    for (int u = 0; u < 4; u++) {
        int c = threadIdx.x + u * 256;
        float t = (v[u] - mean) * rstd * (ap[sc * CDIM + c] + 1.f) + ap[sh * CDIM + c];
        h[(size_t)row * CDIM + c] = __float2half_rn(t);
    }
}

// ================= fp16 mma.sync GEMM: C[M,N] = A[M,K] @ W[N,K]^T =================
// 128x128 CTA tile, BK=32 halfs, 4-stage cp.async, 8 warps (2x4), ldmatrix frags.
#define TC_STAGES 4
#define TC_STR 40                              /* halfs per 32-elem row (+8 pad) */
#define TC_MAT_HALFS (128 * TC_STR)            /* 5120 */
#define TC_STAGE_BYTES (2 * TC_MAT_HALFS * 2)  /* 20480: A then B */
#define TC_SMEM (TC_STAGES * TC_STAGE_BYTES)   /* 81920 */

__global__ __launch_bounds__(256, 2)
void tc_gemm(int K, int N,
             const __half* __restrict__ A, const __half* __restrict__ W,
             const float* __restrict__ bias, void* __restrict__ Cout,
             const float* __restrict__ res, int gate_chunk, int act, int out_half)
{
    extern __shared__ __half smh[];
    const uint32_t sb = smem_u32(smh);
    const int tid = threadIdx.x;
    const int wid = tid >> 5, lane = tid & 31;
    const int wm = wid & 1, wn = wid >> 1;
    const int gid = lane >> 2, tig = lane & 3;
    const int m0 = blockIdx.y * 128, n0 = blockIdx.x * 128;
    const int NC = K >> 5;

    auto load_chunk = [&](int c) {
        const uint32_t base = sb + (c & (TC_STAGES - 1)) * TC_STAGE_BYTES;
        const int k0 = c << 5;
        #pragma unroll
        for (int t = 0; t < 2; t++) {
            int slot = tid + t * 256;        // 0..511
            int row = slot >> 2;             // 0..127
            int q = slot & 3;                // 16B chunk (8 halfs)
            uint32_t off = (uint32_t)(row * TC_STR + q * 8) * 2u;
            cpasync16(base + off, A + (size_t)(m0 + row) * K + k0 + q * 8);
            cpasync16(base + TC_MAT_HALFS * 2 + off, W + (size_t)(n0 + row) * K + k0 + q * 8);
        }
    };

    #pragma unroll
    for (int c = 0; c < TC_STAGES - 1; c++) { load_chunk(c); cp_commit(); }

    float acc[4][4][4];
    #pragma unroll
    for (int i = 0; i < 4; i++)
        #pragma unroll
        for (int j = 0; j < 4; j++)
            #pragma unroll
            for (int u = 0; u < 4; u++) acc[i][j][u] = 0.f;

    const int la_row = (lane & 7) + ((lane >> 3) & 1) * 8;
    const int la_kk  = (lane >> 4) * 8;
    const int lb_row = ((lane >> 4) & 1) * 8 + (lane & 7);
    const int lb_kk  = ((lane >> 3) & 1) * 8;

    for (int c = 0; c < NC; c++) {
        cp_wait2();
        __syncthreads();
        const uint32_t sA = sb + (uint32_t)(c & (TC_STAGES - 1)) * TC_STAGE_BYTES;
        const uint32_t sB = sA + TC_MAT_HALFS * 2;
        #pragma unroll
        for (int ks = 0; ks < 2; ks++) {
            uint32_t a[4][4], bf[4][2];
            #pragma unroll
            for (int mt = 0; mt < 4; mt++) {
                int row = wm * 64 + mt * 16 + la_row;
                ldsm_x4(a[mt][0], a[mt][1], a[mt][2], a[mt][3],
                        sA + (uint32_t)(row * TC_STR + ks * 16 + la_kk) * 2);
            }
            #pragma unroll
            for (int ntp = 0; ntp < 2; ntp++) {
                int row = wn * 32 + ntp * 16 + lb_row;
                ldsm_x4(bf[2 * ntp][0], bf[2 * ntp][1], bf[2 * ntp + 1][0], bf[2 * ntp + 1][1],
                        sB + (uint32_t)(row * TC_STR + ks * 16 + lb_kk) * 2);
            }
            #pragma unroll
            for (int mt = 0; mt < 4; mt++)
                #pragma unroll
                for (int nt = 0; nt < 4; nt++)
                    mma_f16(acc[mt][nt], a[mt][0], a[mt][1], a[mt][2], a[mt][3],
                            bf[nt][0], bf[nt][1]);
        }
        __syncthreads();
        if (c + TC_STAGES - 1 < NC) load_chunk(c + TC_STAGES - 1);
        cp_commit();
    }

    // ---- fused epilogue ----
    #pragma unroll
    for (int mt = 0; mt < 4; mt++) {
        #pragma unroll
        for (int half_i = 0; half_i < 2; half_i++) {
            const int m = m0 + wm * 64 + mt * 16 + gid + half_i * 8;
            const int bb = m >> 11;
            const float* ap = g_ada + bb * 6 * CDIM;
            #pragma unroll
            for (int nt = 0; nt < 4; nt++) {
                const int n = n0 + wn * 32 + nt * 8 + tig * 2;
                float v0 = acc[mt][nt][half_i * 2];
                float v1 = acc[mt][nt][half_i * 2 + 1];
                if (bias) { v0 += bias[n]; v1 += bias[n + 1]; }
                if (act == 1) {  // gelu(v) = v / (1 + e^{-2y}), y = 0.79788..*(v+0.044715 v^3)
                    float y0 = 0.7978845608028654f * fmaf(0.044715f * v0, v0 * v0, v0);
                    float y1 = 0.7978845608028654f * fmaf(0.044715f * v1, v1 * v1, v1);
                    v0 = __fdividef(v0, 1.f + fexp(-2.f * y0));
                    v1 = __fdividef(v1, 1.f + fexp(-2.f * y1));
                }
                if (gate_chunk >= 0) {
                    v0 *= ap[gate_chunk * CDIM + n];
                    v1 *= ap[gate_chunk * CDIM + n + 1];
                }
                if (res) {
                    v0 += res[(size_t)m * N + n];
                    v1 += res[(size_t)m * N + n + 1];
                }
                if (out_half) {
                    *(uint32_t*)((__half*)Cout + (size_t)m * N + n) = f2h2(v0, v1);
                } else {
                    *(float2*)((float*)Cout + (size_t)m * N + n) = make_float2(v0, v1);
                }
            }
        }
    }
}

// ---------------- qkv norm (in-place, half2): L2-normalize q/k + scale ----------------
__global__ __launch_bounds__(256) void qkv_norm_kernel(
    const float* __restrict__ scale_mul)
{
    const int gw = blockIdx.x * 8 + (threadIdx.x >> 5);
    const int lane = threadIdx.x & 31;
    const int h = gw & 15;
    const int t = (gw >> 4) % 3;
    if (t == 2) return;                 // v passes through
    const int bl = gw / 48;
    __half2* p = (__half2*)(g_qkvh + ((size_t)bl * 3 + t) * CDIM + h * DHD);
    float2 v = __half22float2(p[lane]);
    float ss = v.x * v.x + v.y * v.y;
    #pragma unroll
    for (int m = 16; m; m >>= 1) ss += __shfl_xor_sync(0xffffffffu, ss, m);
    float r = rsqrtf(fmaxf(ss, 1e-24f));
    if (t == 0) r *= expf(fminf(scale_mul[h], 4.605170185988092f));
    p[lane] = __floats2half2_rn(v.x * r, v.y * r);
}

// ================= flash attention, fp16 mma, ldmatrix + fragment chaining =================
#define FA_STR 72                                  /* halfs per row */
#define FA_SQ   (128 * FA_STR)
#define FA_SK   (64 * FA_STR)                      /* per stage */
#define FA_SMEM ((FA_SQ + 4 * FA_SK) * 2)          /* Q + 2-stage K + 2-stage V = 55296 B */

__global__ __launch_bounds__(256, 2)
void flash_mma(const __half* __restrict__ abias, __half* __restrict__ out)
{
    extern __shared__ __half fsm[];
    const uint32_t sqb = smem_u32(fsm);             // sQ  [128][72]
    const uint32_t skb = sqb + FA_SQ * 2;           // sK  2 x [64][72]
    const uint32_t svb = skb + 2 * FA_SK * 2;       // sV  2 x [64][72] (natural [kcol][d])

    const int qt = blockIdx.x, bh = blockIdx.y;
    const int b = bh >> 4, h = bh & 15;
    const int tid = threadIdx.x, wid = tid >> 5, lane = tid & 31;
    const int gid = lane >> 2, tig = lane & 3;
    const int qrow0 = qt * 128;
    const int wq0 = wid * 16;

    const int la_row = (lane & 7) + ((lane >> 3) & 1) * 8;
    const int la_kk  = (lane >> 4) * 8;
    const int lb_row = ((lane >> 4) & 1) * 8 + (lane & 7);
    const int lb_kk  = ((lane >> 3) & 1) * 8;

    for (int i = tid; i < 128 * 8; i += 256) {
        int r = i >> 3, c8 = i & 7;
        uint4 v = *(const uint4*)(g_qkvh +
            ((size_t)(b * LSEQ + qrow0 + r) * 3 + 0) * CDIM + h * DHD + c8 * 8);
        *(uint4*)(fsm + r * FA_STR + c8 * 8) = v;
    }

    auto load_kv = [&](int kt) {
        const uint32_t st = (uint32_t)(kt & 1) * FA_SK * 2;
        #pragma unroll
        for (int t = 0; t < 2; t++) {
            int slot = tid + t * 256;
            int r = slot >> 3, c8 = slot & 7;
            const __half* kp = g_qkvh +
                ((size_t)(b * LSEQ + kt * 64 + r) * 3 + 1) * CDIM + h * DHD + c8 * 8;
            uint32_t off = (uint32_t)(r * FA_STR + c8 * 8) * 2u;
            cpasync16(skb + st + off, kp);
            cpasync16(svb + st + off, kp + CDIM);
        }
    };

    load_kv(0); cp_commit();

    float oacc[8][4];
    #pragma unroll
    for (int i = 0; i < 8; i++)
        #pragma unroll
        for (int j = 0; j < 4; j++) oacc[i][j] = 0.f;
    float m0r = -1e30f, m1r = -1e30f, l0 = 0.f, l1 = 0.f;

    const int NT = LSEQ / 64;
    for (int kt = 0; kt < NT; kt++) {
        __syncthreads();
        if (kt + 1 < NT) load_kv(kt + 1);
        cp_commit();
        cp_wait1();
        __syncthreads();

        const uint32_t sKst = skb + (uint32_t)(kt & 1) * FA_SK * 2;
        const uint32_t sVst = svb + (uint32_t)(kt & 1) * FA_SK * 2;

        float sacc[8][4];
        #pragma unroll
        for (int i = 0; i < 8; i++)
            #pragma unroll
            for (int j = 0; j < 4; j++) sacc[i][j] = 0.f;
        #pragma unroll
        for (int ks = 0; ks < 4; ks++) {
            uint32_t a0, a1, a2, a3;
            ldsm_x4(a0, a1, a2, a3,
                sqb + (uint32_t)((wq0 + la_row) * FA_STR + ks * 16 + la_kk) * 2);
            #pragma unroll
            for (int ntp = 0; ntp < 4; ntp++) {
                uint32_t b0, b1, b2, b3;
                ldsm_x4(b0, b1, b2, b3,
                    sKst + (uint32_t)((ntp * 16 + lb_row) * FA_STR + ks * 16 + lb_kk) * 2);
                mma_f16(sacc[2 * ntp],     a0, a1, a2, a3, b0, b1);
                mma_f16(sacc[2 * ntp + 1], a0, a1, a2, a3, b2, b3);
            }
        }
        // + attn_bias (half)
        {
            const __half* bp = abias + (size_t)(qrow0 + wq0) * LSEQ + kt * 64;
            #pragma unroll
            for (int nt = 0; nt < 8; nt++) {
                float2 b01 = __half22float2(*(const __half2*)(bp + (size_t)gid * LSEQ + nt * 8 + 2 * tig));
                float2 b23 = __half22float2(*(const __half2*)(bp + (size_t)(gid + 8) * LSEQ + nt * 8 + 2 * tig));
                sacc[nt][0] += b01.x; sacc[nt][1] += b01.y;
                sacc[nt][2] += b23.x; sacc[nt][3] += b23.y;
            }
        }
        // online softmax (rows gid and gid+8)
        float mx0 = -1e30f, mx1 = -1e30f;
        #pragma unroll
        for (int nt = 0; nt < 8; nt++) {
            mx0 = fmaxf(mx0, fmaxf(sacc[nt][0], sacc[nt][1]));
            mx1 = fmaxf(mx1, fmaxf(sacc[nt][2], sacc[nt][3]));
        }
        mx0 = fmaxf(mx0, __shfl_xor_sync(0xffffffffu, mx0, 1));
        mx0 = fmaxf(mx0, __shfl_xor_sync(0xffffffffu, mx0, 2));
        mx1 = fmaxf(mx1, __shfl_xor_sync(0xffffffffu, mx1, 1));
        mx1 = fmaxf(mx1, __shfl_xor_sync(0xffffffffu, mx1, 2));
        float mn0 = fmaxf(m0r, mx0), mn1 = fmaxf(m1r, mx1);
        float al0 = fexp(m0r - mn0), al1 = fexp(m1r - mn1);
        float rs0 = 0.f, rs1 = 0.f;
        #pragma unroll
        for (int nt = 0; nt < 8; nt++) {
            sacc[nt][0] = fexp(sacc[nt][0] - mn0);
            sacc[nt][1] = fexp(sacc[nt][1] - mn0);
            sacc[nt][2] = fexp(sacc[nt][2] - mn1);
            sacc[nt][3] = fexp(sacc[nt][3] - mn1);
            rs0 += sacc[nt][0] + sacc[nt][1];
            rs1 += sacc[nt][2] + sacc[nt][3];
        }
        rs0 += __shfl_xor_sync(0xffffffffu, rs0, 1);
        rs0 += __shfl_xor_sync(0xffffffffu, rs0, 2);
        rs1 += __shfl_xor_sync(0xffffffffu, rs1, 1);
        rs1 += __shfl_xor_sync(0xffffffffu, rs1, 2);
        l0 = l0 * al0 + rs0; l1 = l1 * al1 + rs1;
        m0r = mn0; m1r = mn1;
        #pragma unroll
        for (int dt = 0; dt < 8; dt++) {
            oacc[dt][0] *= al0; oacc[dt][1] *= al0;
            oacc[dt][2] *= al1; oacc[dt][3] *= al1;
        }
        // O += P V : A fragments chained directly from sacc; B = ldmatrix.trans on natural V
        #pragma unroll
        for (int kc = 0; kc < 4; kc++) {
            uint32_t a0 = f2h2(sacc[2 * kc][0],     sacc[2 * kc][1]);
            uint32_t a1 = f2h2(sacc[2 * kc][2],     sacc[2 * kc][3]);
            uint32_t a2 = f2h2(sacc[2 * kc + 1][0], sacc[2 * kc + 1][1]);
            uint32_t a3 = f2h2(sacc[2 * kc + 1][2], sacc[2 * kc + 1][3]);
            #pragma unroll
            for (int dtp = 0; dtp < 4; dtp++) {
                uint32_t b0, b1, b2, b3;
                int row = kc * 16 + lb_kk + (lane & 7);
                int dcol = dtp * 16 + ((lane >> 4) & 1) * 8;
                ldsm_x4_t(b0, b1, b2, b3,
                    sVst + (uint32_t)(row * FA_STR + dcol) * 2);
                mma_f16(oacc[2 * dtp],     a0, a1, a2, a3, b0, b1);
                mma_f16(oacc[2 * dtp + 1], a0, a1, a2, a3, b2, b3);
            }
        }
    }
    {
        float inv0 = 1.f / l0, inv1 = 1.f / l1;
        const size_t r0 = (size_t)(b * LSEQ + qrow0 + wq0 + gid);
        const size_t r1 = r0 + 8;
        #pragma unroll
        for (int dt = 0; dt < 8; dt++) {
            int col = h * DHD + dt * 8 + 2 * tig;
            *(uint32_t*)(out + r0 * CDIM + col) = f2h2(oacc[dt][0] * inv0, oacc[dt][1] * inv0);
            *(uint32_t*)(out + r1 * CDIM + col) = f2h2(oacc[dt][2] * inv1, oacc[dt][3] * inv1);
        }
    }
}

// ---------------- launch ----------------
extern "C" void kernel_launch(void* const* d_in, const int* in_sizes, int n_in,
                              void* d_out, int out_size)
{
    const float* x         = (const float*)d_in[0];
    const float* cond_BD   = (const float*)d_in[1];
    const float* attn_bias = (const float*)d_in[2];
    const float* qkv_w     = (const float*)d_in[3];
    const float* q_bias    = (const float*)d_in[4];
    const float* v_bias    = (const float*)d_in[5];
    const float* scale_mul = (const float*)d_in[6];
    const float* proj_w    = (const float*)d_in[7];
    const float* proj_b    = (const float*)d_in[8];
    const float* fc1_w     = (const float*)d_in[9];
    const float* fc1_b     = (const float*)d_in[10];
    const float* fc2_w     = (const float*)d_in[11];
    const float* fc2_b     = (const float*)d_in[12];
    const float* ada_w     = (const float*)d_in[13];
    const float* ada_b     = (const float*)d_in[14];
    float* outp = (float*)d_out;

    float *p_x1;
    __half *p_wh, *p_abh, *p_hh, *p_qkvh, *p_attnh, *p_ffh;
    cudaGetSymbolAddress((void**)&p_x1, g_x1);
    cudaGetSymbolAddress((void**)&p_wh, g_wh);
    cudaGetSymbolAddress((void**)&p_abh, g_abh);
    cudaGetSymbolAddress((void**)&p_hh, g_hh);
    cudaGetSymbolAddress((void**)&p_qkvh, g_qkvh);
    cudaGetSymbolAddress((void**)&p_attnh, g_attnh);
    cudaGetSymbolAddress((void**)&p_ffh, g_ffh);
    float* p_bias3;
    cudaGetSymbolAddress((void**)&p_bias3, g_bias3);

    cudaFuncSetAttribute(tc_gemm, cudaFuncAttributeMaxDynamicSharedMemorySize, TC_SMEM);
    cudaFuncSetAttribute(flash_mma, cudaFuncAttributeMaxDynamicSharedMemorySize, FA_SMEM);

    // 0) converts: qkv_w, proj_w, fc1_w, fc2_w, attn_bias  (single kernel)
    {
        const int n0 = 3*CDIM*CDIM/4, n1 = CDIM*CDIM/4, n2 = DFF*CDIM/4,
                  n3 = CDIM*DFF/4, n4 = LSEQ*LSEQ/4;
        const int total = n0 + n1 + n2 + n3 + n4;
        f2h_multi<<<(total + 255)/256, 256>>>(
            (const float4*)qkv_w, (const float4*)proj_w, (const float4*)fc1_w,
            (const float4*)fc2_w, (const float4*)attn_bias,
            (uint2*)(p_wh + WH_QKV), (uint2*)(p_wh + WH_PROJ), (uint2*)(p_wh + WH_FC1),
            (uint2*)(p_wh + WH_FC2), (uint2*)p_abh,
            n0, n1, n2, n3, n4);
    }
    bias3_kernel<<<3 * CDIM / 256, 256>>>(q_bias, v_bias);

    // 1) adaLN coefficients
    ada_kernel<<<dim3(6 * CDIM / 4, BATCH), 128>>>(cond_BD, ada_w, ada_b);
    // 2) h = LN(x)*(s1+1)+sh1   (chunks: g1=0,g2=1,s1=2,s2=3,sh1=4,sh2=5)
    ln_mod_kernel<<<NROWS, 256>>>(x, p_hh, 2, 4);
    // 3) qkv = h @ qkv_w^T + bias3  (half out)
    tc_gemm<<<dim3(3 * CDIM / 128, NROWS / 128), 256, TC_SMEM>>>(
        CDIM, 3 * CDIM, p_hh, p_wh + WH_QKV, p_bias3, p_qkvh, nullptr, -1, 0, 1);
    // 4) per-head L2 norm + scale (in place, half)
    qkv_norm_kernel<<<NROWS * 3 * HEADS / 8, 256>>>(scale_mul);
    // 5) attention (fp16 mma) -> half
    flash_mma<<<dim3(LSEQ / 128, BATCH * HEADS), 256, FA_SMEM>>>(p_abh, p_attnh);
    // 6) x1 = x + (attn @ proj_w^T + proj_b) * g1  (f32 out)
    tc_gemm<<<dim3(CDIM / 128, NROWS / 128), 256, TC_SMEM>>>(
        CDIM, CDIM, p_attnh, p_wh + WH_PROJ, proj_b, p_x1, x, 0, 0, 0);
    // 7) h = LN(x1)*(s2+1)+sh2
    ln_mod_kernel<<<NROWS, 256>>>(p_x1, p_hh, 3, 5);
    // 8) ff = gelu(h @ fc1_w^T + fc1_b)  (half out)
    tc_gemm<<<dim3(DFF / 128, NROWS / 128), 256, TC_SMEM>>>(
        CDIM, DFF, p_hh, p_wh + WH_FC1, fc1_b, p_ffh, nullptr, -1, 1, 1);
    // 9) out = x1 + (ff @ fc2_w^T + fc2_b) * g2  (f32 out)
    tc_gemm<<<dim3(CDIM / 128, NROWS / 128), 256, TC_SMEM>>>(
        DFF, CDIM, p_ffh, p_wh + WH_FC2, fc2_b, outp, p_x1, 1, 0, 0);
}

// round 13
// speedup vs baseline: 1.0246x; 1.0246x over previous
#include <cuda_runtime.h>
#include <cuda_fp16.h>
#include <cstdint>
#include <cstddef>

#define CDIM 1024
#define HEADS 16
#define DHD 64
#define LSEQ 2048
#define BATCH 2
#define DFF 4096
#define NROWS (BATCH*LSEQ)   /* 4096 */

// ---------------- scratch (device globals: alloc-free) ----------------
__device__ float  g_ada[BATCH * 6 * CDIM];                  // [B,6,C]
__device__ float  g_bias3[3 * CDIM];                        // [q_bias, 0, v_bias]
__device__ float  g_x1[(size_t)NROWS * CDIM];               // residual stream f32
__device__ __half g_wh[12582912];                           // converted weights
__device__ __half g_abh[(size_t)LSEQ * LSEQ];               // attn_bias (half)
__device__ __half g_hh[(size_t)NROWS * CDIM];               // LN-mod out (half)
__device__ __half g_qkvh[(size_t)NROWS * 3 * CDIM];         // qkv (half)
__device__ __half g_attnh[(size_t)NROWS * CDIM];            // attn out (half)
__device__ __half g_ffh[(size_t)NROWS * DFF];               // fc1+gelu out (half)

#define WH_QKV  0
#define WH_PROJ 3145728
#define WH_FC1  4194304
#define WH_FC2  8388608

// ================= helpers =================
__device__ __forceinline__ uint32_t smem_u32(const void* p) {
    uint32_t a;
    asm("{ .reg .u64 t; cvta.to.shared.u64 t, %1; cvt.u32.u64 %0, t; }" : "=r"(a) : "l"(p));
    return a;
}
__device__ __forceinline__ void cpasync16(uint32_t dst, const void* src) {
    asm volatile("cp.async.cg.shared.global [%0], [%1], 16;" :: "r"(dst), "l"(src));
}
__device__ __forceinline__ void cp_commit() { asm volatile("cp.async.commit_group;" ::: "memory"); }
__device__ __forceinline__ void cp_wait2()  { asm volatile("cp.async.wait_group 2;" ::: "memory"); }
__device__ __forceinline__ void cp_wait0()  { asm volatile("cp.async.wait_group 0;" ::: "memory"); }

__device__ __forceinline__ uint32_t f2h2(float x, float y) {
    __half2 h = __floats2half2_rn(x, y);
    return *reinterpret_cast<uint32_t*>(&h);
}
__device__ __forceinline__ void mma_f16(float* c,
    uint32_t a0, uint32_t a1, uint32_t a2, uint32_t a3, uint32_t b0, uint32_t b1)
{
    asm volatile(
        "mma.sync.aligned.m16n8k16.row.col.f32.f16.f16.f32 "
        "{%0,%1,%2,%3},{%4,%5,%6,%7},{%8,%9},{%0,%1,%2,%3};"
        : "+f"(c[0]), "+f"(c[1]), "+f"(c[2]), "+f"(c[3])
        : "r"(a0), "r"(a1), "r"(a2), "r"(a3), "r"(b0), "r"(b1));
}
__device__ __forceinline__ void ldsm_x4(uint32_t& r0, uint32_t& r1, uint32_t& r2, uint32_t& r3,
                                        uint32_t addr) {
    asm volatile("ldmatrix.sync.aligned.m8n8.x4.shared.b16 {%0,%1,%2,%3}, [%4];"
        : "=r"(r0), "=r"(r1), "=r"(r2), "=r"(r3) : "r"(addr));
}
__device__ __forceinline__ void ldsm_x4_t(uint32_t& r0, uint32_t& r1, uint32_t& r2, uint32_t& r3,
                                          uint32_t addr) {
    asm volatile("ldmatrix.sync.aligned.m8n8.x4.trans.shared.b16 {%0,%1,%2,%3}, [%4];"
        : "=r"(r0), "=r"(r1), "=r"(r2), "=r"(r3) : "r"(addr));
}

// FMA-pipe exp (no MUFU), clamped both sides
__device__ __forceinline__ float fexp(float x) {
    float t = fminf(fmaxf(x, -87.f), 87.f) * 1.4426950408889634f;
    float z = __fadd_rn(t, 12582912.0f);
    float n = __fsub_rn(z, 12582912.0f);
    int ni = (__float_as_int(z) & 0x7FFFFF) - 0x400000;
    float c = (t - n) * 0.6931471805599453f;
    float p = 8.3333333e-3f;
    p = fmaf(p, c, 4.1666667e-2f);
    p = fmaf(p, c, 0.16666667f);
    p = fmaf(p, c, 0.5f);
    p = fmaf(p, c, 1.0f);
    p = fmaf(p, c, 1.0f);
    return p * __int_as_float((ni + 127) << 23);
}

// ---------------- combined f32 -> f16 convert: 4 weights + attn_bias ----------------
__global__ __launch_bounds__(256) void f2h_multi(
    const float4* __restrict__ s0, const float4* __restrict__ s1,
    const float4* __restrict__ s2, const float4* __restrict__ s3,
    const float4* __restrict__ s4,
    uint2* __restrict__ d0, uint2* __restrict__ d1, uint2* __restrict__ d2,
    uint2* __restrict__ d3, uint2* __restrict__ d4,
    int n0, int n1, int n2, int n3, int n4)
{
    int i = blockIdx.x * 256 + threadIdx.x;
    const float4* s; uint2* d;
    if (i < n0) { s = s0; d = d0; }
    else if ((i -= n0) < n1) { s = s1; d = d1; }
    else if ((i -= n1) < n2) { s = s2; d = d2; }
    else if ((i -= n2) < n3) { s = s3; d = d3; }
    else if ((i -= n3) < n4) { s = s4; d = d4; }
    else return;
    float4 v = s[i];
    d[i] = make_uint2(f2h2(v.x, v.y), f2h2(v.z, v.w));
}

// ---------------- bias3 = [q_bias, 0, v_bias] ----------------
__global__ __launch_bounds__(256) void bias3_kernel(
    const float* __restrict__ qb, const float* __restrict__ vb)
{
    int i = blockIdx.x * 256 + threadIdx.x;
    float v = 0.f;
    if (i < CDIM) v = qb[i];
    else if (i >= 2 * CDIM) v = vb[i - 2 * CDIM];
    g_bias3[i] = v;
}

// ---------------- ada = silu(cond) @ ada_w.T + ada_b ----------------
__global__ __launch_bounds__(128) void ada_kernel(
    const float* __restrict__ cond, const float* __restrict__ ada_w,
    const float* __restrict__ ada_b)
{
    const int warp = threadIdx.x >> 5;
    const int lane = threadIdx.x & 31;
    const int o = blockIdx.x * 4 + warp;
    const int b = blockIdx.y;
    const float* wr = ada_w + (size_t)o * CDIM;
    const float* cr = cond + b * CDIM;
    float s = 0.f;
    for (int k = lane; k < CDIM; k += 32) {
        float c = cr[k];
        float si = __fdividef(c, 1.f + fexp(-c));
        s += si * wr[k];
    }
    #pragma unroll
    for (int m = 16; m; m >>= 1) s += __shfl_xor_sync(0xffffffffu, s, m);
    if (lane == 0) g_ada[b * 6 * CDIM + o] = s + ada_b[o];
}

// ---------------- h = LN(x) * (scale+1) + shift  (half out, float4 path) ----------------
__global__ __launch_bounds__(256) void ln_mod_kernel(
    const float* __restrict__ x, __half* __restrict__ h, int sc, int sh)
{
    __shared__ float red[2];
    __shared__ float ws[16];
    const int row = blockIdx.x;
    const int b = row >> 11;
    const float4 v = ((const float4*)(x + (size_t)row * CDIM))[threadIdx.x];
    float s  = v.x + v.y + v.z + v.w;
    float ss = v.x * v.x + v.y * v.y + v.z * v.z + v.w * v.w;
    #pragma unroll
    for (int m = 16; m; m >>= 1) {
        s  += __shfl_xor_sync(0xffffffffu, s, m);
        ss += __shfl_xor_sync(0xffffffffu, ss, m);
    }
    int w = threadIdx.x >> 5, ln = threadIdx.x & 31;
    if (ln == 0) { ws[w] = s; ws[8 + w] = ss; }
    __syncthreads();
    if (threadIdx.x == 0) {
        float S = 0.f, SS = 0.f;
        #pragma unroll
        for (int i = 0; i < 8; i++) { S += ws[i]; SS += ws[8 + i]; }
        float m = S * (1.f / CDIM);
        float var = SS * (1.f / CDIM) - m * m;
        red[0] = m;
        red[1] = rsqrtf(var + 1e-6f);
    }
    __syncthreads();
    const float mean = red[0], rstd = red[1];
    const float* ap = g_ada + b * 6 * CDIM;
    const float4 sv = ((const float4*)(ap + sc * CDIM))[threadIdx.x];
    const float4 hv = ((const float4*)(ap + sh * CDIM))[threadIdx.x];
    float t0 = (v.x - mean) * rstd * (sv.x + 1.f) + hv.x;
    float t1 = (v.y - mean) * rstd * (sv.y + 1.f) + hv.y;
    float t2 = (v.z - mean) * rstd * (sv.z + 1.f) + hv.z;
    float t3 = (v.w - mean) * rstd * (sv.w + 1.f) + hv.w;
    ((uint2*)(h + (size_t)row * CDIM))[threadIdx.x] =
        make_uint2(f2h2(t0, t1), f2h2(t2, t3));
}

// ================= fp16 mma.sync GEMM: C[M,N] = A[M,K] @ W[N,K]^T =================
// 128x128 CTA tile, BK=32 halfs, 4-stage cp.async, 8 warps (2x4), ldmatrix frags.
// ONE barrier per K-chunk: with a 4-stage ring the prefetch target (c+3)&3 == (c-1)&3
// holds data every warp finished before the entry barrier of iteration c.
#define TC_STAGES 4
#define TC_STR 40                              /* halfs per 32-elem row (+8 pad) */
#define TC_MAT_HALFS (128 * TC_STR)            /* 5120 */
#define TC_STAGE_BYTES (2 * TC_MAT_HALFS * 2)  /* 20480: A then B */
#define TC_SMEM (TC_STAGES * TC_STAGE_BYTES)   /* 81920 */

__global__ __launch_bounds__(256, 2)
void tc_gemm(int K, int N,
             const __half* __restrict__ A, const __half* __restrict__ W,
             const float* __restrict__ bias, void* __restrict__ Cout,
             const float* __restrict__ res, int gate_chunk, int act, int out_half)
{
    extern __shared__ __half smh[];
    const uint32_t sb = smem_u32(smh);
    const int tid = threadIdx.x;
    const int wid = tid >> 5, lane = tid & 31;
    const int wm = wid & 1, wn = wid >> 1;
    const int gid = lane >> 2, tig = lane & 3;
    const int m0 = blockIdx.y * 128, n0 = blockIdx.x * 128;
    const int NC = K >> 5;

    auto load_chunk = [&](int c) {
        const uint32_t base = sb + (c & (TC_STAGES - 1)) * TC_STAGE_BYTES;
        const int k0 = c << 5;
        #pragma unroll
        for (int t = 0; t < 2; t++) {
            int slot = tid + t * 256;        // 0..511
            int row = slot >> 2;             // 0..127
            int q = slot & 3;                // 16B chunk (8 halfs)
            uint32_t off = (uint32_t)(row * TC_STR + q * 8) * 2u;
            cpasync16(base + off, A + (size_t)(m0 + row) * K + k0 + q * 8);
            cpasync16(base + TC_MAT_HALFS * 2 + off, W + (size_t)(n0 + row) * K + k0 + q * 8);
        }
    };

    #pragma unroll
    for (int c = 0; c < TC_STAGES - 1; c++) { load_chunk(c); cp_commit(); }

    float acc[4][4][4];
    #pragma unroll
    for (int i = 0; i < 4; i++)
        #pragma unroll
        for (int j = 0; j < 4; j++)
            #pragma unroll
            for (int u = 0; u < 4; u++) acc[i][j][u] = 0.f;

    const int la_row = (lane & 7) + ((lane >> 3) & 1) * 8;
    const int la_kk  = (lane >> 4) * 8;
    const int lb_row = ((lane >> 4) & 1) * 8 + (lane & 7);
    const int lb_kk  = ((lane >> 3) & 1) * 8;

    for (int c = 0; c < NC; c++) {
        cp_wait2();
        __syncthreads();
        if (c + TC_STAGES - 1 < NC) load_chunk(c + TC_STAGES - 1);
        cp_commit();
        const uint32_t sA = sb + (uint32_t)(c & (TC_STAGES - 1)) * TC_STAGE_BYTES;
        const uint32_t sB = sA + TC_MAT_HALFS * 2;
        #pragma unroll
        for (int ks = 0; ks < 2; ks++) {
            uint32_t a[4][4], bf[4][2];
            #pragma unroll
            for (int mt = 0; mt < 4; mt++) {
                int row = wm * 64 + mt * 16 + la_row;
                ldsm_x4(a[mt][0], a[mt][1], a[mt][2], a[mt][3],
                        sA + (uint32_t)(row * TC_STR + ks * 16 + la_kk) * 2);
            }
            #pragma unroll
            for (int ntp = 0; ntp < 2; ntp++) {
                int row = wn * 32 + ntp * 16 + lb_row;
                ldsm_x4(bf[2 * ntp][0], bf[2 * ntp][1], bf[2 * ntp + 1][0], bf[2 * ntp + 1][1],
                        sB + (uint32_t)(row * TC_STR + ks * 16 + lb_kk) * 2);
            }
            #pragma unroll
            for (int mt = 0; mt < 4; mt++)
                #pragma unroll
                for (int nt = 0; nt < 4; nt++)
                    mma_f16(acc[mt][nt], a[mt][0], a[mt][1], a[mt][2], a[mt][3],
                            bf[nt][0], bf[nt][1]);
        }
    }

    // ---- fused epilogue ----
    #pragma unroll
    for (int mt = 0; mt < 4; mt++) {
        #pragma unroll
        for (int half_i = 0; half_i < 2; half_i++) {
            const int m = m0 + wm * 64 + mt * 16 + gid + half_i * 8;
            const int bb = m >> 11;
            const float* ap = g_ada + bb * 6 * CDIM;
            #pragma unroll
            for (int nt = 0; nt < 4; nt++) {
                const int n = n0 + wn * 32 + nt * 8 + tig * 2;
                float v0 = acc[mt][nt][half_i * 2];
                float v1 = acc[mt][nt][half_i * 2 + 1];
                if (bias) { v0 += bias[n]; v1 += bias[n + 1]; }
                if (act == 1) {  // gelu(v) = v / (1 + e^{-2y})
                    float y0 = 0.7978845608028654f * fmaf(0.044715f * v0, v0 * v0, v0);
                    float y1 = 0.7978845608028654f * fmaf(0.044715f * v1, v1 * v1, v1);
                    v0 = __fdividef(v0, 1.f + fexp(-2.f * y0));
                    v1 = __fdividef(v1, 1.f + fexp(-2.f * y1));
                }
                if (gate_chunk >= 0) {
                    v0 *= ap[gate_chunk * CDIM + n];
                    v1 *= ap[gate_chunk * CDIM + n + 1];
                }
                if (res) {
                    v0 += res[(size_t)m * N + n];
                    v1 += res[(size_t)m * N + n + 1];
                }
                if (out_half) {
                    *(uint32_t*)((__half*)Cout + (size_t)m * N + n) = f2h2(v0, v1);
                } else {
                    *(float2*)((float*)Cout + (size_t)m * N + n) = make_float2(v0, v1);
                }
            }
        }
    }
}

// ---------------- qkv norm (in-place, half2): L2-normalize q/k + scale; q,k planes only ----------------
__global__ __launch_bounds__(256) void qkv_norm_kernel(
    const float* __restrict__ scale_mul)
{
    const int gw = blockIdx.x * 8 + (threadIdx.x >> 5);   // over NROWS*2*HEADS warps
    const int lane = threadIdx.x & 31;
    const int h = gw & 15;
    const int t = (gw >> 4) & 1;
    const int bl = gw >> 5;
    __half2* p = (__half2*)(g_qkvh + ((size_t)bl * 3 + t) * CDIM + h * DHD);
    float2 v = __half22float2(p[lane]);
    float ss = v.x * v.x + v.y * v.y;
    #pragma unroll
    for (int m = 16; m; m >>= 1) ss += __shfl_xor_sync(0xffffffffu, ss, m);
    float r = rsqrtf(fmaxf(ss, 1e-24f));
    if (t == 0) r *= expf(fminf(scale_mul[h], 4.605170185988092f));
    p[lane] = __floats2half2_rn(v.x * r, v.y * r);
}

// ================= flash attention, fp16 mma, ldmatrix + fragment chaining =================
// ONE barrier per K-tile: prefetch after the entry barrier targets the stage all
// warps finished reading in iteration kt-1.
#define FA_STR 72                                  /* halfs per row */
#define FA_SQ   (128 * FA_STR)
#define FA_SK   (64 * FA_STR)                      /* per stage */
#define FA_SMEM ((FA_SQ + 4 * FA_SK) * 2)          /* Q + 2-stage K + 2-stage V = 55296 B */

__global__ __launch_bounds__(256, 2)
void flash_mma(const __half* __restrict__ abias, __half* __restrict__ out)
{
    extern __shared__ __half fsm[];
    const uint32_t sqb = smem_u32(fsm);             // sQ  [128][72]
    const uint32_t skb = sqb + FA_SQ * 2;           // sK  2 x [64][72]
    const uint32_t svb = skb + 2 * FA_SK * 2;       // sV  2 x [64][72] (natural [kcol][d])

    const int qt = blockIdx.x, bh = blockIdx.y;
    const int b = bh >> 4, h = bh & 15;
    const int tid = threadIdx.x, wid = tid >> 5, lane = tid & 31;
    const int gid = lane >> 2, tig = lane & 3;
    const int qrow0 = qt * 128;
    const int wq0 = wid * 16;

    const int la_row = (lane & 7) + ((lane >> 3) & 1) * 8;
    const int la_kk  = (lane >> 4) * 8;
    const int lb_row = ((lane >> 4) & 1) * 8 + (lane & 7);
    const int lb_kk  = ((lane >> 3) & 1) * 8;

    for (int i = tid; i < 128 * 8; i += 256) {
        int r = i >> 3, c8 = i & 7;
        uint4 v = *(const uint4*)(g_qkvh +
            ((size_t)(b * LSEQ + qrow0 + r) * 3 + 0) * CDIM + h * DHD + c8 * 8);
        *(uint4*)(fsm + r * FA_STR + c8 * 8) = v;
    }

    auto load_kv = [&](int kt) {
        const uint32_t st = (uint32_t)(kt & 1) * FA_SK * 2;
        #pragma unroll
        for (int t = 0; t < 2; t++) {
            int slot = tid + t * 256;
            int r = slot >> 3, c8 = slot & 7;
            const __half* kp = g_qkvh +
                ((size_t)(b * LSEQ + kt * 64 + r) * 3 + 1) * CDIM + h * DHD + c8 * 8;
            uint32_t off = (uint32_t)(r * FA_STR + c8 * 8) * 2u;
            cpasync16(skb + st + off, kp);
            cpasync16(svb + st + off, kp + CDIM);
        }
    };

    load_kv(0); cp_commit();

    float oacc[8][4];
    #pragma unroll
    for (int i = 0; i < 8; i++)
        #pragma unroll
        for (int j = 0; j < 4; j++) oacc[i][j] = 0.f;
    float m0r = -1e30f, m1r = -1e30f, l0 = 0.f, l1 = 0.f;

    const int NT = LSEQ / 64;
    for (int kt = 0; kt < NT; kt++) {
        cp_wait0();                               // stage kt resident
        __syncthreads();                          // visibility + all warps done with kt-1
        if (kt + 1 < NT) load_kv(kt + 1);         // targets stage (kt+1)&1 — free per barrier
        cp_commit();

        const uint32_t sKst = skb + (uint32_t)(kt & 1) * FA_SK * 2;
        const uint32_t sVst = svb + (uint32_t)(kt & 1) * FA_SK * 2;

        float sacc[8][4];
        #pragma unroll
        for (int i = 0; i < 8; i++)
            #pragma unroll
            for (int j = 0; j < 4; j++) sacc[i][j] = 0.f;
        #pragma unroll
        for (int ks = 0; ks < 4; ks++) {
            uint32_t a0, a1, a2, a3;
            ldsm_x4(a0, a1, a2, a3,
                sqb + (uint32_t)((wq0 + la_row) * FA_STR + ks * 16 + la_kk) * 2);
            #pragma unroll
            for (int ntp = 0; ntp < 4; ntp++) {
                uint32_t b0, b1, b2, b3;
                ldsm_x4(b0, b1, b2, b3,
                    sKst + (uint32_t)((ntp * 16 + lb_row) * FA_STR + ks * 16 + lb_kk) * 2);
                mma_f16(sacc[2 * ntp],     a0, a1, a2, a3, b0, b1);
                mma_f16(sacc[2 * ntp + 1], a0, a1, a2, a3, b2, b3);
            }
        }
        // + attn_bias (half)
        {
            const __half* bp = abias + (size_t)(qrow0 + wq0) * LSEQ + kt * 64;
            #pragma unroll
            for (int nt = 0; nt < 8; nt++) {
                float2 b01 = __half22float2(*(const __half2*)(bp + (size_t)gid * LSEQ + nt * 8 + 2 * tig));
                float2 b23 = __half22float2(*(const __half2*)(bp + (size_t)(gid + 8) * LSEQ + nt * 8 + 2 * tig));
                sacc[nt][0] += b01.x; sacc[nt][1] += b01.y;
                sacc[nt][2] += b23.x; sacc[nt][3] += b23.y;
            }
        }
        // online softmax (rows gid and gid+8)
        float mx0 = -1e30f, mx1 = -1e30f;
        #pragma unroll
        for (int nt = 0; nt < 8; nt++) {
            mx0 = fmaxf(mx0, fmaxf(sacc[nt][0], sacc[nt][1]));
            mx1 = fmaxf(mx1, fmaxf(sacc[nt][2], sacc[nt][3]));
        }
        mx0 = fmaxf(mx0, __shfl_xor_sync(0xffffffffu, mx0, 1));
        mx0 = fmaxf(mx0, __shfl_xor_sync(0xffffffffu, mx0, 2));
        mx1 = fmaxf(mx1, __shfl_xor_sync(0xffffffffu, mx1, 1));
        mx1 = fmaxf(mx1, __shfl_xor_sync(0xffffffffu, mx1, 2));
        float mn0 = fmaxf(m0r, mx0), mn1 = fmaxf(m1r, mx1);
        float al0 = fexp(m0r - mn0), al1 = fexp(m1r - mn1);
        float rs0 = 0.f, rs1 = 0.f;
        #pragma unroll
        for (int nt = 0; nt < 8; nt++) {
            sacc[nt][0] = fexp(sacc[nt][0] - mn0);
            sacc[nt][1] = fexp(sacc[nt][1] - mn0);
            sacc[nt][2] = fexp(sacc[nt][2] - mn1);
            sacc[nt][3] = fexp(sacc[nt][3] - mn1);
            rs0 += sacc[nt][0] + sacc[nt][1];
            rs1 += sacc[nt][2] + sacc[nt][3];
        }
        rs0 += __shfl_xor_sync(0xffffffffu, rs0, 1);
        rs0 += __shfl_xor_sync(0xffffffffu, rs0, 2);
        rs1 += __shfl_xor_sync(0xffffffffu, rs1, 1);
        rs1 += __shfl_xor_sync(0xffffffffu, rs1, 2);
        l0 = l0 * al0 + rs0; l1 = l1 * al1 + rs1;
        m0r = mn0; m1r = mn1;
        #pragma unroll
        for (int dt = 0; dt < 8; dt++) {
            oacc[dt][0] *= al0; oacc[dt][1] *= al0;
            oacc[dt][2] *= al1; oacc[dt][3] *= al1;
        }
        // O += P V : A fragments chained directly from sacc; B = ldmatrix.trans on natural V
        #pragma unroll
        for (int kc = 0; kc < 4; kc++) {
            uint32_t a0 = f2h2(sacc[2 * kc][0],     sacc[2 * kc][1]);
            uint32_t a1 = f2h2(sacc[2 * kc][2],     sacc[2 * kc][3]);
            uint32_t a2 = f2h2(sacc[2 * kc + 1][0], sacc[2 * kc + 1][1]);
            uint32_t a3 = f2h2(sacc[2 * kc + 1][2], sacc[2 * kc + 1][3]);
            #pragma unroll
            for (int dtp = 0; dtp < 4; dtp++) {
                uint32_t b0, b1, b2, b3;
                int row = kc * 16 + lb_kk + (lane & 7);
                int dcol = dtp * 16 + ((lane >> 4) & 1) * 8;
                ldsm_x4_t(b0, b1, b2, b3,
                    sVst + (uint32_t)(row * FA_STR + dcol) * 2);
                mma_f16(oacc[2 * dtp],     a0, a1, a2, a3, b0, b1);
                mma_f16(oacc[2 * dtp + 1], a0, a1, a2, a3, b2, b3);
            }
        }
    }
    {
        float inv0 = 1.f / l0, inv1 = 1.f / l1;
        const size_t r0 = (size_t)(b * LSEQ + qrow0 + wq0 + gid);
        const size_t r1 = r0 + 8;
        #pragma unroll
        for (int dt = 0; dt < 8; dt++) {
            int col = h * DHD + dt * 8 + 2 * tig;
            *(uint32_t*)(out + r0 * CDIM + col) = f2h2(oacc[dt][0] * inv0, oacc[dt][1] * inv0);
            *(uint32_t*)(out + r1 * CDIM + col) = f2h2(oacc[dt][2] * inv1, oacc[dt][3] * inv1);
        }
    }
}

// ---------------- launch ----------------
extern "C" void kernel_launch(void* const* d_in, const int* in_sizes, int n_in,
                              void* d_out, int out_size)
{
    const float* x         = (const float*)d_in[0];
    const float* cond_BD   = (const float*)d_in[1];
    const float* attn_bias = (const float*)d_in[2];
    const float* qkv_w     = (const float*)d_in[3];
    const float* q_bias    = (const float*)d_in[4];
    const float* v_bias    = (const float*)d_in[5];
    const float* scale_mul = (const float*)d_in[6];
    const float* proj_w    = (const float*)d_in[7];
    const float* proj_b    = (const float*)d_in[8];
    const float* fc1_w     = (const float*)d_in[9];
    const float* fc1_b     = (const float*)d_in[10];
    const float* fc2_w     = (const float*)d_in[11];
    const float* fc2_b     = (const float*)d_in[12];
    const float* ada_w     = (const float*)d_in[13];
    const float* ada_b     = (const float*)d_in[14];
    float* outp = (float*)d_out;

    float *p_x1;
    __half *p_wh, *p_abh, *p_hh, *p_qkvh, *p_attnh, *p_ffh;
    cudaGetSymbolAddress((void**)&p_x1, g_x1);
    cudaGetSymbolAddress((void**)&p_wh, g_wh);
    cudaGetSymbolAddress((void**)&p_abh, g_abh);
    cudaGetSymbolAddress((void**)&p_hh, g_hh);
    cudaGetSymbolAddress((void**)&p_qkvh, g_qkvh);
    cudaGetSymbolAddress((void**)&p_attnh, g_attnh);
    cudaGetSymbolAddress((void**)&p_ffh, g_ffh);
    float* p_bias3;
    cudaGetSymbolAddress((void**)&p_bias3, g_bias3);

    cudaFuncSetAttribute(tc_gemm, cudaFuncAttributeMaxDynamicSharedMemorySize, TC_SMEM);
    cudaFuncSetAttribute(flash_mma, cudaFuncAttributeMaxDynamicSharedMemorySize, FA_SMEM);

    // 0) converts: qkv_w, proj_w, fc1_w, fc2_w, attn_bias  (single kernel)
    {
        const int n0 = 3*CDIM*CDIM/4, n1 = CDIM*CDIM/4, n2 = DFF*CDIM/4,
                  n3 = CDIM*DFF/4, n4 = LSEQ*LSEQ/4;
        const int total = n0 + n1 + n2 + n3 + n4;
        f2h_multi<<<(total + 255)/256, 256>>>(
            (const float4*)qkv_w, (const float4*)proj_w, (const float4*)fc1_w,
            (const float4*)fc2_w, (const float4*)attn_bias,
            (uint2*)(p_wh + WH_QKV), (uint2*)(p_wh + WH_PROJ), (uint2*)(p_wh + WH_FC1),
            (uint2*)(p_wh + WH_FC2), (uint2*)p_abh,
            n0, n1, n2, n3, n4);
    }
    bias3_kernel<<<3 * CDIM / 256, 256>>>(q_bias, v_bias);

    // 1) adaLN coefficients
    ada_kernel<<<dim3(6 * CDIM / 4, BATCH), 128>>>(cond_BD, ada_w, ada_b);
    // 2) h = LN(x)*(s1+1)+sh1   (chunks: g1=0,g2=1,s1=2,s2=3,sh1=4,sh2=5)
    ln_mod_kernel<<<NROWS, 256>>>(x, p_hh, 2, 4);
    // 3) qkv = h @ qkv_w^T + bias3  (half out)
    tc_gemm<<<dim3(3 * CDIM / 128, NROWS / 128), 256, TC_SMEM>>>(
        CDIM, 3 * CDIM, p_hh, p_wh + WH_QKV, p_bias3, p_qkvh, nullptr, -1, 0, 1);
    // 4) per-head L2 norm + scale (in place, half; q,k planes only)
    qkv_norm_kernel<<<NROWS * 2 * HEADS / 8, 256>>>(scale_mul);
    // 5) attention (fp16 mma) -> half
    flash_mma<<<dim3(LSEQ / 128, BATCH * HEADS), 256, FA_SMEM>>>(p_abh, p_attnh);
    // 6) x1 = x + (attn @ proj_w^T + proj_b) * g1  (f32 out)
    tc_gemm<<<dim3(CDIM / 128, NROWS / 128), 256, TC_SMEM>>>(
        CDIM, CDIM, p_attnh, p_wh + WH_PROJ, proj_b, p_x1, x, 0, 0, 0);
    // 7) h = LN(x1)*(s2+1)+sh2
    ln_mod_kernel<<<NROWS, 256>>>(p_x1, p_hh, 3, 5);
    // 8) ff = gelu(h @ fc1_w^T + fc1_b)  (half out)
    tc_gemm<<<dim3(DFF / 128, NROWS / 128), 256, TC_SMEM>>>(
        CDIM, DFF, p_hh, p_wh + WH_FC1, fc1_b, p_ffh, nullptr, -1, 1, 1);
    // 9) out = x1 + (ff @ fc2_w^T + fc2_b) * g2  (f32 out)
    tc_gemm<<<dim3(CDIM / 128, NROWS / 128), 256, TC_SMEM>>>(
        DFF, CDIM, p_ffh, p_wh + WH_FC2, fc2_b, outp, p_x1, 1, 0, 0);
}

// round 16
// speedup vs baseline: 1.0281x; 1.0034x over previous
#include <cuda_runtime.h>
#include <cuda_fp16.h>
#include <cstdint>
#include <cstddef>

#define CDIM 1024
#define HEADS 16
#define DHD 64
#define LSEQ 2048
#define BATCH 2
#define DFF 4096
#define NROWS (BATCH*LSEQ)   /* 4096 */

// ---------------- scratch (device globals: alloc-free) ----------------
__device__ float  g_ada[BATCH * 6 * CDIM];                  // [B,6,C]
__device__ float  g_bias3[3 * CDIM];                        // [q_bias, 0, v_bias]
__device__ float  g_x1[(size_t)NROWS * CDIM];               // residual stream f32
__device__ __half g_wh[12582912];                           // converted weights
__device__ __half g_abh[(size_t)LSEQ * LSEQ];               // attn_bias (half)
__device__ __half g_hh[(size_t)NROWS * CDIM];               // LN-mod out (half)
__device__ __half g_qkvh[(size_t)NROWS * 3 * CDIM];         // qkv (half)
__device__ __half g_attnh[(size_t)NROWS * CDIM];            // attn out (half)
__device__ __half g_ffh[(size_t)NROWS * DFF];               // fc1+gelu out (half)

#define WH_QKV  0
#define WH_PROJ 3145728
#define WH_FC1  4194304
#define WH_FC2  8388608

// f2h element counts (float4 units)
#define N4_QKV  (3*CDIM*CDIM/4)
#define N4_PROJ (CDIM*CDIM/4)
#define N4_FC1  (DFF*CDIM/4)
#define N4_FC2  (CDIM*DFF/4)
#define N4_AB   (LSEQ*LSEQ/4)
#define N4_TOT  (N4_QKV + N4_PROJ + N4_FC1 + N4_FC2 + N4_AB)
#define NB_F2H  ((N4_TOT + 255) / 256)        /* 16384 */
#define NB_B3   12
#define NB_ADA  1536                          /* 12288 warps, 8 warps/block */

// ================= helpers =================
__device__ __forceinline__ uint32_t smem_u32(const void* p) {
    uint32_t a;
    asm("{ .reg .u64 t; cvta.to.shared.u64 t, %1; cvt.u32.u64 %0, t; }" : "=r"(a) : "l"(p));
    return a;
}
__device__ __forceinline__ void cpasync16(uint32_t dst, const void* src) {
    asm volatile("cp.async.cg.shared.global [%0], [%1], 16;" :: "r"(dst), "l"(src));
}
__device__ __forceinline__ void cp_commit() { asm volatile("cp.async.commit_group;" ::: "memory"); }
__device__ __forceinline__ void cp_wait2()  { asm volatile("cp.async.wait_group 2;" ::: "memory"); }
__device__ __forceinline__ void cp_wait0()  { asm volatile("cp.async.wait_group 0;" ::: "memory"); }

__device__ __forceinline__ uint32_t f2h2(float x, float y) {
    __half2 h = __floats2half2_rn(x, y);
    return *reinterpret_cast<uint32_t*>(&h);
}
__device__ __forceinline__ void mma_f16(float* c,
    uint32_t a0, uint32_t a1, uint32_t a2, uint32_t a3, uint32_t b0, uint32_t b1)
{
    asm volatile(
        "mma.sync.aligned.m16n8k16.row.col.f32.f16.f16.f32 "
        "{%0,%1,%2,%3},{%4,%5,%6,%7},{%8,%9},{%0,%1,%2,%3};"
        : "+f"(c[0]), "+f"(c[1]), "+f"(c[2]), "+f"(c[3])
        : "r"(a0), "r"(a1), "r"(a2), "r"(a3), "r"(b0), "r"(b1));
}
__device__ __forceinline__ void ldsm_x4(uint32_t& r0, uint32_t& r1, uint32_t& r2, uint32_t& r3,
                                        uint32_t addr) {
    asm volatile("ldmatrix.sync.aligned.m8n8.x4.shared.b16 {%0,%1,%2,%3}, [%4];"
        : "=r"(r0), "=r"(r1), "=r"(r2), "=r"(r3) : "r"(addr));
}
__device__ __forceinline__ void ldsm_x4_t(uint32_t& r0, uint32_t& r1, uint32_t& r2, uint32_t& r3,
                                          uint32_t addr) {
    asm volatile("ldmatrix.sync.aligned.m8n8.x4.trans.shared.b16 {%0,%1,%2,%3}, [%4];"
        : "=r"(r0), "=r"(r1), "=r"(r2), "=r"(r3) : "r"(addr));
}

// FMA-pipe exp (no MUFU), clamped both sides
__device__ __forceinline__ float fexp(float x) {
    float t = fminf(fmaxf(x, -87.f), 87.f) * 1.4426950408889634f;
    float z = __fadd_rn(t, 12582912.0f);
    float n = __fsub_rn(z, 12582912.0f);
    int ni = (__float_as_int(z) & 0x7FFFFF) - 0x400000;
    float c = (t - n) * 0.6931471805599453f;
    float p = 8.3333333e-3f;
    p = fmaf(p, c, 4.1666667e-2f);
    p = fmaf(p, c, 0.16666667f);
    p = fmaf(p, c, 0.5f);
    p = fmaf(p, c, 1.0f);
    p = fmaf(p, c, 1.0f);
    return p * __int_as_float((ni + 127) << 23);
}

// ---------------- merged prologue: f2h converts + bias3 + ada (independent jobs) ----------------
__global__ __launch_bounds__(256) void prologue_kernel(
    const float4* __restrict__ qkv_w, const float4* __restrict__ proj_w,
    const float4* __restrict__ fc1_w, const float4* __restrict__ fc2_w,
    const float4* __restrict__ abias,
    const float* __restrict__ qb, const float* __restrict__ vb,
    const float* __restrict__ cond, const float* __restrict__ ada_w,
    const float* __restrict__ ada_b)
{
    const int blk = blockIdx.x;
    if (blk < NB_F2H) {
        // ---- f32 -> f16 converts ----
        int i = blk * 256 + threadIdx.x;
        const float4* s; uint2* d;
        __half* p_wh = g_wh;
        if (i < N4_QKV) { s = qkv_w; d = (uint2*)(p_wh + WH_QKV); }
        else if ((i -= N4_QKV) < N4_PROJ) { s = proj_w; d = (uint2*)(p_wh + WH_PROJ); }
        else if ((i -= N4_PROJ) < N4_FC1) { s = fc1_w; d = (uint2*)(p_wh + WH_FC1); }
        else if ((i -= N4_FC1) < N4_FC2) { s = fc2_w; d = (uint2*)(p_wh + WH_FC2); }
        else if ((i -= N4_FC2) < N4_AB) { s = abias; d = (uint2*)g_abh; }
        else return;
        float4 v = s[i];
        d[i] = make_uint2(f2h2(v.x, v.y), f2h2(v.z, v.w));
    } else if (blk < NB_F2H + NB_B3) {
        // ---- bias3 = [q_bias, 0, v_bias] ----
        int i = (blk - NB_F2H) * 256 + threadIdx.x;
        float v = 0.f;
        if (i < CDIM) v = qb[i];
        else if (i >= 2 * CDIM) v = vb[i - 2 * CDIM];
        g_bias3[i] = v;
    } else {
        // ---- ada = silu(cond) @ ada_w.T + ada_b ----
        const int gw = (blk - NB_F2H - NB_B3) * 8 + (threadIdx.x >> 5);  // 0..12287
        const int lane = threadIdx.x & 31;
        const int b = gw & 1;
        const int o = gw >> 1;                 // 0..6143
        const float* wr = ada_w + (size_t)o * CDIM;
        const float* cr = cond + b * CDIM;
        float s = 0.f;
        for (int k = lane; k < CDIM; k += 32) {
            float c = cr[k];
            float si = __fdividef(c, 1.f + fexp(-c));
            s += si * wr[k];
        }
        #pragma unroll
        for (int m = 16; m; m >>= 1) s += __shfl_xor_sync(0xffffffffu, s, m);
        if (lane == 0) g_ada[b * 6 * CDIM + o] = s + ada_b[o];
    }
}

// ---------------- h = LN(x) * (scale+1) + shift  (half out, single barrier) ----------------
__global__ __launch_bounds__(256) void ln_mod_kernel(
    const float* __restrict__ x, __half* __restrict__ h, int sc, int sh)
{
    __shared__ float ws[16];
    const int row = blockIdx.x;
    const int b = row >> 11;
    const float4 v = ((const float4*)(x + (size_t)row * CDIM))[threadIdx.x];
    float s  = v.x + v.y + v.z + v.w;
    float ss = v.x * v.x + v.y * v.y + v.z * v.z + v.w * v.w;
    #pragma unroll
    for (int m = 16; m; m >>= 1) {
        s  += __shfl_xor_sync(0xffffffffu, s, m);
        ss += __shfl_xor_sync(0xffffffffu, ss, m);
    }
    int w = threadIdx.x >> 5, ln = threadIdx.x & 31;
    if (ln == 0) { ws[w] = s; ws[8 + w] = ss; }
    __syncthreads();
    float S = 0.f, SS = 0.f;
    #pragma unroll
    for (int i = 0; i < 8; i++) { S += ws[i]; SS += ws[8 + i]; }
    const float mean = S * (1.f / CDIM);
    const float rstd = rsqrtf(SS * (1.f / CDIM) - mean * mean + 1e-6f);
    const float* ap = g_ada + b * 6 * CDIM;
    const float4 sv = ((const float4*)(ap + sc * CDIM))[threadIdx.x];
    const float4 hv = ((const float4*)(ap + sh * CDIM))[threadIdx.x];
    float t0 = (v.x - mean) * rstd * (sv.x + 1.f) + hv.x;
    float t1 = (v.y - mean) * rstd * (sv.y + 1.f) + hv.y;
    float t2 = (v.z - mean) * rstd * (sv.z + 1.f) + hv.z;
    float t3 = (v.w - mean) * rstd * (sv.w + 1.f) + hv.w;
    ((uint2*)(h + (size_t)row * CDIM))[threadIdx.x] =
        make_uint2(f2h2(t0, t1), f2h2(t2, t3));
}

// ================= fp16 mma.sync GEMM: C[M,N] = A[M,K] @ W[N,K]^T =================
#define TC_STAGES 4
#define TC_STR 40                              /* halfs per 32-elem row (+8 pad) */
#define TC_MAT_HALFS (128 * TC_STR)            /* 5120 */
#define TC_STAGE_BYTES (2 * TC_MAT_HALFS * 2)  /* 20480: A then B */
#define TC_SMEM (TC_STAGES * TC_STAGE_BYTES)   /* 81920 */

__global__ __launch_bounds__(256, 2)
void tc_gemm(int K, int N,
             const __half* __restrict__ A, const __half* __restrict__ W,
             const float* __restrict__ bias, void* __restrict__ Cout,
             const float* __restrict__ res, int gate_chunk, int act, int out_half)
{
    extern __shared__ __half smh[];
    const uint32_t sb = smem_u32(smh);
    const int tid = threadIdx.x;
    const int wid = tid >> 5, lane = tid & 31;
    const int wm = wid & 1, wn = wid >> 1;
    const int gid = lane >> 2, tig = lane & 3;
    const int m0 = blockIdx.y * 128, n0 = blockIdx.x * 128;
    const int NC = K >> 5;

    auto load_chunk = [&](int c) {
        const uint32_t base = sb + (c & (TC_STAGES - 1)) * TC_STAGE_BYTES;
        const int k0 = c << 5;
        #pragma unroll
        for (int t = 0; t < 2; t++) {
            int slot = tid + t * 256;
            int row = slot >> 2;
            int q = slot & 3;
            uint32_t off = (uint32_t)(row * TC_STR + q * 8) * 2u;
            cpasync16(base + off, A + (size_t)(m0 + row) * K + k0 + q * 8);
            cpasync16(base + TC_MAT_HALFS * 2 + off, W + (size_t)(n0 + row) * K + k0 + q * 8);
        }
    };

    #pragma unroll
    for (int c = 0; c < TC_STAGES - 1; c++) { load_chunk(c); cp_commit(); }

    float acc[4][4][4];
    #pragma unroll
    for (int i = 0; i < 4; i++)
        #pragma unroll
        for (int j = 0; j < 4; j++)
            #pragma unroll
            for (int u = 0; u < 4; u++) acc[i][j][u] = 0.f;

    const int la_row = (lane & 7) + ((lane >> 3) & 1) * 8;
    const int la_kk  = (lane >> 4) * 8;
    const int lb_row = ((lane >> 4) & 1) * 8 + (lane & 7);
    const int lb_kk  = ((lane >> 3) & 1) * 8;

    for (int c = 0; c < NC; c++) {
        cp_wait2();
        __syncthreads();
        if (c + TC_STAGES - 1 < NC) load_chunk(c + TC_STAGES - 1);
        cp_commit();
        const uint32_t sA = sb + (uint32_t)(c & (TC_STAGES - 1)) * TC_STAGE_BYTES;
        const uint32_t sB = sA + TC_MAT_HALFS * 2;
        #pragma unroll
        for (int ks = 0; ks < 2; ks++) {
            uint32_t a[4][4], bf[4][2];
            #pragma unroll
            for (int mt = 0; mt < 4; mt++) {
                int row = wm * 64 + mt * 16 + la_row;
                ldsm_x4(a[mt][0], a[mt][1], a[mt][2], a[mt][3],
                        sA + (uint32_t)(row * TC_STR + ks * 16 + la_kk) * 2);
            }
            #pragma unroll
            for (int ntp = 0; ntp < 2; ntp++) {
                int row = wn * 32 + ntp * 16 + lb_row;
                ldsm_x4(bf[2 * ntp][0], bf[2 * ntp][1], bf[2 * ntp + 1][0], bf[2 * ntp + 1][1],
                        sB + (uint32_t)(row * TC_STR + ks * 16 + lb_kk) * 2);
            }
            #pragma unroll
            for (int mt = 0; mt < 4; mt++)
                #pragma unroll
                for (int nt = 0; nt < 4; nt++)
                    mma_f16(acc[mt][nt], a[mt][0], a[mt][1], a[mt][2], a[mt][3],
                            bf[nt][0], bf[nt][1]);
        }
    }

    // ---- fused epilogue ----
    #pragma unroll
    for (int mt = 0; mt < 4; mt++) {
        #pragma unroll
        for (int half_i = 0; half_i < 2; half_i++) {
            const int m = m0 + wm * 64 + mt * 16 + gid + half_i * 8;
            const int bb = m >> 11;
            const float* ap = g_ada + bb * 6 * CDIM;
            #pragma unroll
            for (int nt = 0; nt < 4; nt++) {
                const int n = n0 + wn * 32 + nt * 8 + tig * 2;
                float v0 = acc[mt][nt][half_i * 2];
                float v1 = acc[mt][nt][half_i * 2 + 1];
                if (bias) { v0 += bias[n]; v1 += bias[n + 1]; }
                if (act == 1) {  // gelu(v) = v / (1 + e^{-2y})
                    float y0 = 0.7978845608028654f * fmaf(0.044715f * v0, v0 * v0, v0);
                    float y1 = 0.7978845608028654f * fmaf(0.044715f * v1, v1 * v1, v1);
                    v0 = __fdividef(v0, 1.f + fexp(-2.f * y0));
                    v1 = __fdividef(v1, 1.f + fexp(-2.f * y1));
                }
                if (gate_chunk >= 0) {
                    v0 *= ap[gate_chunk * CDIM + n];
                    v1 *= ap[gate_chunk * CDIM + n + 1];
                }
                if (res) {
                    v0 += res[(size_t)m * N + n];
                    v1 += res[(size_t)m * N + n + 1];
                }
                if (out_half) {
                    *(uint32_t*)((__half*)Cout + (size_t)m * N + n) = f2h2(v0, v1);
                } else {
                    *(float2*)((float*)Cout + (size_t)m * N + n) = make_float2(v0, v1);
                }
            }
        }
    }
}

// ---------------- qkv norm (in-place, half2): L2-normalize q/k + scale; q,k planes only ----------------
__global__ __launch_bounds__(256) void qkv_norm_kernel(
    const float* __restrict__ scale_mul)
{
    const int gw = blockIdx.x * 8 + (threadIdx.x >> 5);
    const int lane = threadIdx.x & 31;
    const int h = gw & 15;
    const int t = (gw >> 4) & 1;
    const int bl = gw >> 5;
    __half2* p = (__half2*)(g_qkvh + ((size_t)bl * 3 + t) * CDIM + h * DHD);
    float2 v = __half22float2(p[lane]);
    float ss = v.x * v.x + v.y * v.y;
    #pragma unroll
    for (int m = 16; m; m >>= 1) ss += __shfl_xor_sync(0xffffffffu, ss, m);
    float r = rsqrtf(fmaxf(ss, 1e-24f));
    if (t == 0) r *= expf(fminf(scale_mul[h], 4.605170185988092f));
    p[lane] = __floats2half2_rn(v.x * r, v.y * r);
}

// ================= flash attention, fp16 mma, ldmatrix + fragment chaining =================
#define FA_STR 72                                  /* halfs per row */
#define FA_SQ   (128 * FA_STR)
#define FA_SK   (64 * FA_STR)                      /* per stage */
#define FA_SMEM ((FA_SQ + 4 * FA_SK) * 2)          /* Q + 2-stage K + 2-stage V = 55296 B */

__global__ __launch_bounds__(256, 2)
void flash_mma(const __half* __restrict__ abias, __half* __restrict__ out)
{
    extern __shared__ __half fsm[];
    const uint32_t sqb = smem_u32(fsm);             // sQ  [128][72]
    const uint32_t skb = sqb + FA_SQ * 2;           // sK  2 x [64][72]
    const uint32_t svb = skb + 2 * FA_SK * 2;       // sV  2 x [64][72] (natural [kcol][d])

    const int qt = blockIdx.x, bh = blockIdx.y;
    const int b = bh >> 4, h = bh & 15;
    const int tid = threadIdx.x, wid = tid >> 5, lane = tid & 31;
    const int gid = lane >> 2, tig = lane & 3;
    const int qrow0 = qt * 128;
    const int wq0 = wid * 16;

    const int la_row = (lane & 7) + ((lane >> 3) & 1) * 8;
    const int la_kk  = (lane >> 4) * 8;
    const int lb_row = ((lane >> 4) & 1) * 8 + (lane & 7);
    const int lb_kk  = ((lane >> 3) & 1) * 8;

    for (int i = tid; i < 128 * 8; i += 256) {
        int r = i >> 3, c8 = i & 7;
        uint4 v = *(const uint4*)(g_qkvh +
            ((size_t)(b * LSEQ + qrow0 + r) * 3 + 0) * CDIM + h * DHD + c8 * 8);
        *(uint4*)(fsm + r * FA_STR + c8 * 8) = v;
    }

    auto load_kv = [&](int kt) {
        const uint32_t st = (uint32_t)(kt & 1) * FA_SK * 2;
        #pragma unroll
        for (int t = 0; t < 2; t++) {
            int slot = tid + t * 256;
            int r = slot >> 3, c8 = slot & 7;
            const __half* kp = g_qkvh +
                ((size_t)(b * LSEQ + kt * 64 + r) * 3 + 1) * CDIM + h * DHD + c8 * 8;
            uint32_t off = (uint32_t)(r * FA_STR + c8 * 8) * 2u;
            cpasync16(skb + st + off, kp);
            cpasync16(svb + st + off, kp + CDIM);
        }
    };

    load_kv(0); cp_commit();

    float oacc[8][4];
    #pragma unroll
    for (int i = 0; i < 8; i++)
        #pragma unroll
        for (int j = 0; j < 4; j++) oacc[i][j] = 0.f;
    float m0r = -1e30f, m1r = -1e30f, l0 = 0.f, l1 = 0.f;

    const int NT = LSEQ / 64;
    for (int kt = 0; kt < NT; kt++) {
        cp_wait0();                               // stage kt resident
        __syncthreads();                          // visibility + all warps done with kt-1
        if (kt + 1 < NT) load_kv(kt + 1);
        cp_commit();

        // hoist attn_bias loads (L2-resident); consumed after the mma block
        uint32_t braw[16];
        {
            const __half* bp = abias + (size_t)(qrow0 + wq0) * LSEQ + kt * 64;
            #pragma unroll
            for (int nt = 0; nt < 8; nt++) {
                braw[nt]     = *(const uint32_t*)(bp + (size_t)gid * LSEQ + nt * 8 + 2 * tig);
                braw[8 + nt] = *(const uint32_t*)(bp + (size_t)(gid + 8) * LSEQ + nt * 8 + 2 * tig);
            }
        }

        const uint32_t sKst = skb + (uint32_t)(kt & 1) * FA_SK * 2;
        const uint32_t sVst = svb + (uint32_t)(kt & 1) * FA_SK * 2;

        float sacc[8][4];
        #pragma unroll
        for (int i = 0; i < 8; i++)
            #pragma unroll
            for (int j = 0; j < 4; j++) sacc[i][j] = 0.f;
        #pragma unroll
        for (int ks = 0; ks < 4; ks++) {
            uint32_t a0, a1, a2, a3;
            ldsm_x4(a0, a1, a2, a3,
                sqb + (uint32_t)((wq0 + la_row) * FA_STR + ks * 16 + la_kk) * 2);
            #pragma unroll
            for (int ntp = 0; ntp < 4; ntp++) {
                uint32_t b0, b1, b2, b3;
                ldsm_x4(b0, b1, b2, b3,
                    sKst + (uint32_t)((ntp * 16 + lb_row) * FA_STR + ks * 16 + lb_kk) * 2);
                mma_f16(sacc[2 * ntp],     a0, a1, a2, a3, b0, b1);
                mma_f16(sacc[2 * ntp + 1], a0, a1, a2, a3, b2, b3);
            }
        }
        // + attn_bias (from hoisted regs)
        #pragma unroll
        for (int nt = 0; nt < 8; nt++) {
            float2 b01 = __half22float2(*(const __half2*)&braw[nt]);
            float2 b23 = __half22float2(*(const __half2*)&braw[8 + nt]);
            sacc[nt][0] += b01.x; sacc[nt][1] += b01.y;
            sacc[nt][2] += b23.x; sacc[nt][3] += b23.y;
        }
        // online softmax (rows gid and gid+8)
        float mx0 = -1e30f, mx1 = -1e30f;
        #pragma unroll
        for (int nt = 0; nt < 8; nt++) {
            mx0 = fmaxf(mx0, fmaxf(sacc[nt][0], sacc[nt][1]));
            mx1 = fmaxf(mx1, fmaxf(sacc[nt][2], sacc[nt][3]));
        }
        mx0 = fmaxf(mx0, __shfl_xor_sync(0xffffffffu, mx0, 1));
        mx0 = fmaxf(mx0, __shfl_xor_sync(0xffffffffu, mx0, 2));
        mx1 = fmaxf(mx1, __shfl_xor_sync(0xffffffffu, mx1, 1));
        mx1 = fmaxf(mx1, __shfl_xor_sync(0xffffffffu, mx1, 2));
        float mn0 = fmaxf(m0r, mx0), mn1 = fmaxf(m1r, mx1);
        float al0 = fexp(m0r - mn0), al1 = fexp(m1r - mn1);
        float rs0 = 0.f, rs1 = 0.f;
        #pragma unroll
        for (int nt = 0; nt < 8; nt++) {
            sacc[nt][0] = fexp(sacc[nt][0] - mn0);
            sacc[nt][1] = fexp(sacc[nt][1] - mn0);
            sacc[nt][2] = fexp(sacc[nt][2] - mn1);
            sacc[nt][3] = fexp(sacc[nt][3] - mn1);
            rs0 += sacc[nt][0] + sacc[nt][1];
            rs1 += sacc[nt][2] + sacc[nt][3];
        }
        rs0 += __shfl_xor_sync(0xffffffffu, rs0, 1);
        rs0 += __shfl_xor_sync(0xffffffffu, rs0, 2);
        rs1 += __shfl_xor_sync(0xffffffffu, rs1, 1);
        rs1 += __shfl_xor_sync(0xffffffffu, rs1, 2);
        l0 = l0 * al0 + rs0; l1 = l1 * al1 + rs1;
        m0r = mn0; m1r = mn1;
        #pragma unroll
        for (int dt = 0; dt < 8; dt++) {
            oacc[dt][0] *= al0; oacc[dt][1] *= al0;
            oacc[dt][2] *= al1; oacc[dt][3] *= al1;
        }
        // O += P V : A fragments chained directly from sacc; B = ldmatrix.trans on natural V
        #pragma unroll
        for (int kc = 0; kc < 4; kc++) {
            uint32_t a0 = f2h2(sacc[2 * kc][0],     sacc[2 * kc][1]);
            uint32_t a1 = f2h2(sacc[2 * kc][2],     sacc[2 * kc][3]);
            uint32_t a2 = f2h2(sacc[2 * kc + 1][0], sacc[2 * kc + 1][1]);
            uint32_t a3 = f2h2(sacc[2 * kc + 1][2], sacc[2 * kc + 1][3]);
            #pragma unroll
            for (int dtp = 0; dtp < 4; dtp++) {
                uint32_t b0, b1, b2, b3;
                int row = kc * 16 + lb_kk + (lane & 7);
                int dcol = dtp * 16 + ((lane >> 4) & 1) * 8;
                ldsm_x4_t(b0, b1, b2, b3,
                    sVst + (uint32_t)(row * FA_STR + dcol) * 2);
                mma_f16(oacc[2 * dtp],     a0, a1, a2, a3, b0, b1);
                mma_f16(oacc[2 * dtp + 1], a0, a1, a2, a3, b2, b3);
            }
        }
    }
    {
        float inv0 = 1.f / l0, inv1 = 1.f / l1;
        const size_t r0 = (size_t)(b * LSEQ + qrow0 + wq0 + gid);
        const size_t r1 = r0 + 8;
        #pragma unroll
        for (int dt = 0; dt < 8; dt++) {
            int col = h * DHD + dt * 8 + 2 * tig;
            *(uint32_t*)(out + r0 * CDIM + col) = f2h2(oacc[dt][0] * inv0, oacc[dt][1] * inv0);
            *(uint32_t*)(out + r1 * CDIM + col) = f2h2(oacc[dt][2] * inv1, oacc[dt][3] * inv1);
        }
    }
}

// ---------------- launch ----------------
extern "C" void kernel_launch(void* const* d_in, const int* in_sizes, int n_in,
                              void* d_out, int out_size)
{
    const float* x         = (const float*)d_in[0];
    const float* cond_BD   = (const float*)d_in[1];
    const float* attn_bias = (const float*)d_in[2];
    const float* qkv_w     = (const float*)d_in[3];
    const float* q_bias    = (const float*)d_in[4];
    const float* v_bias    = (const float*)d_in[5];
    const float* scale_mul = (const float*)d_in[6];
    const float* proj_w    = (const float*)d_in[7];
    const float* proj_b    = (const float*)d_in[8];
    const float* fc1_w     = (const float*)d_in[9];
    const float* fc1_b     = (const float*)d_in[10];
    const float* fc2_w     = (const float*)d_in[11];
    const float* fc2_b     = (const float*)d_in[12];
    const float* ada_w     = (const float*)d_in[13];
    const float* ada_b     = (const float*)d_in[14];
    float* outp = (float*)d_out;

    float *p_x1;
    __half *p_wh, *p_abh, *p_hh, *p_qkvh, *p_attnh, *p_ffh;
    cudaGetSymbolAddress((void**)&p_x1, g_x1);
    cudaGetSymbolAddress((void**)&p_wh, g_wh);
    cudaGetSymbolAddress((void**)&p_abh, g_abh);
    cudaGetSymbolAddress((void**)&p_hh, g_hh);
    cudaGetSymbolAddress((void**)&p_qkvh, g_qkvh);
    cudaGetSymbolAddress((void**)&p_attnh, g_attnh);
    cudaGetSymbolAddress((void**)&p_ffh, g_ffh);
    float* p_bias3;
    cudaGetSymbolAddress((void**)&p_bias3, g_bias3);

    cudaFuncSetAttribute(tc_gemm, cudaFuncAttributeMaxDynamicSharedMemorySize, TC_SMEM);
    cudaFuncSetAttribute(flash_mma, cudaFuncAttributeMaxDynamicSharedMemorySize, FA_SMEM);

    // 0) merged prologue: weight/bias converts + bias3 + ada  (independent jobs, one launch)
    prologue_kernel<<<NB_F2H + NB_B3 + NB_ADA, 256>>>(
        (const float4*)qkv_w, (const float4*)proj_w, (const float4*)fc1_w,
        (const float4*)fc2_w, (const float4*)attn_bias,
        q_bias, v_bias, cond_BD, ada_w, ada_b);

    // 1) h = LN(x)*(s1+1)+sh1   (chunks: g1=0,g2=1,s1=2,s2=3,sh1=4,sh2=5)
    ln_mod_kernel<<<NROWS, 256>>>(x, p_hh, 2, 4);
    // 2) qkv = h @ qkv_w^T + bias3  (half out)
    tc_gemm<<<dim3(3 * CDIM / 128, NROWS / 128), 256, TC_SMEM>>>(
        CDIM, 3 * CDIM, p_hh, p_wh + WH_QKV, p_bias3, p_qkvh, nullptr, -1, 0, 1);
    // 3) per-head L2 norm + scale (in place, half; q,k planes only)
    qkv_norm_kernel<<<NROWS * 2 * HEADS / 8, 256>>>(scale_mul);
    // 4) attention (fp16 mma) -> half
    flash_mma<<<dim3(LSEQ / 128, BATCH * HEADS), 256, FA_SMEM>>>(p_abh, p_attnh);
    // 5) x1 = x + (attn @ proj_w^T + proj_b) * g1  (f32 out)
    tc_gemm<<<dim3(CDIM / 128, NROWS / 128), 256, TC_SMEM>>>(
        CDIM, CDIM, p_attnh, p_wh + WH_PROJ, proj_b, p_x1, x, 0, 0, 0);
    // 6) h = LN(x1)*(s2+1)+sh2
    ln_mod_kernel<<<NROWS, 256>>>(p_x1, p_hh, 3, 5);
    // 7) ff = gelu(h @ fc1_w^T + fc1_b)  (half out)
    tc_gemm<<<dim3(DFF / 128, NROWS / 128), 256, TC_SMEM>>>(
        CDIM, DFF, p_hh, p_wh + WH_FC1, fc1_b, p_ffh, nullptr, -1, 1, 1);
    // 8) out = x1 + (ff @ fc2_w^T + fc2_b) * g2  (f32 out)
    tc_gemm<<<dim3(CDIM / 128, NROWS / 128), 256, TC_SMEM>>>(
        DFF, CDIM, p_ffh, p_wh + WH_FC2, fc2_b, outp, p_x1, 1, 0, 0);
}